// round 16
// baseline (speedup 1.0000x reference)
#include <cuda_runtime.h>
#include <cuda_fp16.h>
#include <cstdint>

#define SEQ 2048
#define HD  64
#define NBH 32

#define SWZ(x) ((x) ^ (((x) >> 3) & 0x70))
#define NEG_INF __int_as_float(0xff800000)

// per-row softmax denominators (phase1 -> phase2)
__device__ float g_l[NBH * SEQ];

__device__ __forceinline__ uint32_t smem_u32(const void* p) {
    uint32_t a;
    asm("{ .reg .u64 t; cvta.to.shared.u64 t, %1; cvt.u32.u64 %0, t; }"
        : "=r"(a) : "l"(p));
    return a;
}
__device__ __forceinline__ void ldsm4(uint32_t* d, uint32_t a) {
    asm volatile("ldmatrix.sync.aligned.m8n8.x4.shared.b16 {%0,%1,%2,%3}, [%4];"
        : "=r"(d[0]), "=r"(d[1]), "=r"(d[2]), "=r"(d[3]) : "r"(a));
}
__device__ __forceinline__ void ldsm4t(uint32_t* d, uint32_t a) {
    asm volatile("ldmatrix.sync.aligned.m8n8.x4.trans.shared.b16 {%0,%1,%2,%3}, [%4];"
        : "=r"(d[0]), "=r"(d[1]), "=r"(d[2]), "=r"(d[3]) : "r"(a));
}
__device__ __forceinline__ void mma_f16(float* c, const uint32_t* a,
                                        uint32_t b0, uint32_t b1) {
    asm volatile(
        "mma.sync.aligned.m16n8k16.row.col.f32.f16.f16.f32 "
        "{%0,%1,%2,%3}, {%4,%5,%6,%7}, {%8,%9}, {%0,%1,%2,%3};"
        : "+f"(c[0]), "+f"(c[1]), "+f"(c[2]), "+f"(c[3])
        : "r"(a[0]), "r"(a[1]), "r"(a[2]), "r"(a[3]), "r"(b0), "r"(b1));
}
__device__ __forceinline__ uint32_t pack2h(float x0, float x1) {
    __half2 h = __floats2half2_rn(x0, x1);
    return *reinterpret_cast<uint32_t*>(&h);
}
__device__ __forceinline__ uint32_t swzrow(int r) {
    uint32_t x = (uint32_t)r << 7;
    return x ^ ((x >> 3) & 0x70);
}
__device__ __forceinline__ float ex2(float x) {
    float r;
    asm("ex2.approx.ftz.f32 %0, %1;" : "=f"(r) : "f"(x));
    return r;
}

// Q pre-scale: (1/8) * log2(e) -> scores in log2 domain -> ex2
#define QSCALE 0.1803368801111204f

// ===========================================================================
// PHASE 1 kernel: rowsums -> g_l, O = (E@V)/l, zero-fill P upper cols.
// smem: QF 0..16K (persistent), K dbuf 16K..48K, V dbuf 48K..80K. 2 CTAs/SM.
// ===========================================================================
#define KBUF(b) (16384u + (b) * 16384u)
#define VBUF(b) (49152u + (b) * 16384u)

__global__ __launch_bounds__(256, 2) void k_p1(
    const float* __restrict__ Q, const float* __restrict__ K,
    const float* __restrict__ V, const float* __restrict__ mask,
    const int* __restrict__ mask_now,
    float* __restrict__ P, float* __restrict__ O)
{
    extern __shared__ char sm[];
    const uint32_t smb = smem_u32(sm);
    const int tid = threadIdx.x, lane = tid & 31, warp = tid >> 5;
    const int g = lane >> 3, r8 = lane & 7;
    const int qt = 15 - blockIdx.x, bh = blockIdx.y, b = bh >> 4;
    const int q0 = qt * 128;
    const int mn = mask_now[0];

    const int base_elem = (tid >> 4) * HD + (tid & 15) * 4;
    const uint32_t cvt0 = SWZ((uint32_t)((tid >> 4) * 128 + (tid & 15) * 8));

    {
        const float* Qg = Q + ((size_t)bh * SEQ + q0) * HD + base_elem;
        const float* Kg = K + (size_t)bh * SEQ * HD + base_elem;
        const float* Vg = V + (size_t)bh * SEQ * HD + base_elem;
        #pragma unroll
        for (int s = 0; s < 8; s++) {
            uint32_t off = cvt0 + s * 2048;
            float4 v = *(const float4*)(Qg + s * 1024);
            *(uint2*)(sm + 0 + off) = make_uint2(
                pack2h(v.x * QSCALE, v.y * QSCALE),
                pack2h(v.z * QSCALE, v.w * QSCALE));
            v = *(const float4*)(Kg + s * 1024);
            *(uint2*)(sm + KBUF(0) + off) = make_uint2(
                pack2h(v.x, v.y), pack2h(v.z, v.w));
            v = *(const float4*)(Vg + s * 1024);
            *(uint2*)(sm + VBUF(0) + off) = make_uint2(
                pack2h(v.x, v.y), pack2h(v.z, v.w));
        }
    }

    // zero-fill P cols [q0+128, SEQ)
    {
        const int c0 = q0 + 128;
        const int w = (SEQ - c0) >> 2;
        const float4 z4 = make_float4(0.f, 0.f, 0.f, 0.f);
        for (int r = warp; r < 128; r += 8) {
            float4* rowp = (float4*)(P + ((size_t)bh * SEQ + q0 + r) * SEQ + c0);
            for (int cc = lane; cc < w; cc += 32)
                __stcs(rowp + cc, z4);
        }
    }

    const int rl = warp * 16 + (lane >> 2), rh = rl + 8;
    const int qrl = q0 + rl, qrh = q0 + rh;
    const float biasl = (mask[(size_t)b * SEQ + qrl] != 0.f) ? 0.f : NEG_INF;
    const float biash = (mask[(size_t)b * SEQ + qrh] != 0.f) ? 0.f : NEG_INF;
    const int dcol = 2 * (lane & 3);
    const int tcl = qrl - mn - dcol;
    const int tch = qrh - mn - dcol;

    const uint32_t cbq = (uint32_t)(lane & 8) << 1;
    const uint32_t cbv = (uint32_t)(g >> 1) << 4;
    const uint32_t ka0 = swzrow(((g >> 1) << 3) + r8);
    const uint32_t va0 = swzrow(((g & 1) << 3) + r8);
    const uint32_t qrowswz = swzrow(warp * 16 + ((g & 1) << 3) + r8);

    __syncthreads();

    uint32_t qf[4][4];
    #pragma unroll
    for (int s = 0; s < 4; s++)
        ldsm4(qf[s], smb + (qrowswz ^ (cbv | (s << 5))));

    float o[8][4];
    #pragma unroll
    for (int j = 0; j < 8; j++)
        o[j][0] = o[j][1] = o[j][2] = o[j][3] = 0.f;
    float rsl = 0.f, rsh = 0.f;

    for (int t = 0; t <= qt; t++) {
        const int cur = t & 1, nxt = cur ^ 1;
        const bool hasNext = (t < qt);
        const uint32_t Kc = smb + KBUF(cur);
        const uint32_t Vc = smb + VBUF(cur);
        const int k0 = t * 128;
        const bool diag = (t == qt);
        const float* Kg = K + ((size_t)bh * SEQ + k0 + 128) * HD + base_elem;
        const float* Vg = V + ((size_t)bh * SEQ + k0 + 128) * HD + base_elem;

        #pragma unroll
        for (int h = 0; h < 4; h++) {
            float4 pk[2], pv[2];
            if (hasNext) {
                #pragma unroll
                for (int u = 0; u < 2; u++) {
                    pk[u] = *(const float4*)(Kg + (2 * h + u) * 1024);
                    pv[u] = *(const float4*)(Vg + (2 * h + u) * 1024);
                }
            }

            if (!(diag && (2 * h > warp))) {
                float c[4][4];
                #pragma unroll
                for (int j = 0; j < 4; j++) {
                    c[j][0] = c[j][1] = biasl;
                    c[j][2] = c[j][3] = biash;
                }

                #pragma unroll
                for (int s = 0; s < 4; s++) {
                    #pragma unroll
                    for (int pp = 0; pp < 2; pp++) {
                        uint32_t kh[4];
                        ldsm4(kh, Kc + ((ka0 + ((uint32_t)(2 * h + pp) << 11)) ^ (cbq | (s << 5))));
                        mma_f16(c[2 * pp],     qf[s], kh[0], kh[1]);
                        mma_f16(c[2 * pp + 1], qf[s], kh[2], kh[3]);
                    }
                }

                if (!diag) {
                    #pragma unroll
                    for (int jl = 0; jl < 4; jl++) {
                        c[jl][0] = ex2(c[jl][0]);
                        c[jl][1] = ex2(c[jl][1]);
                        c[jl][2] = ex2(c[jl][2]);
                        c[jl][3] = ex2(c[jl][3]);
                        rsl += c[jl][0] + c[jl][1];
                        rsh += c[jl][2] + c[jl][3];
                    }
                } else {
                    #pragma unroll
                    for (int jl = 0; jl < 4; jl++) {
                        int bs = k0 + h * 32 + jl * 8;
                        c[jl][0] = (bs <= tcl    ) ? ex2(c[jl][0]) : 0.f;
                        c[jl][1] = (bs <= tcl - 1) ? ex2(c[jl][1]) : 0.f;
                        c[jl][2] = (bs <= tch    ) ? ex2(c[jl][2]) : 0.f;
                        c[jl][3] = (bs <= tch - 1) ? ex2(c[jl][3]) : 0.f;
                        rsl += c[jl][0] + c[jl][1];
                        rsh += c[jl][2] + c[jl][3];
                    }
                }

                #pragma unroll
                for (int sl = 0; sl < 2; sl++) {
                    uint32_t af[4];
                    af[0] = pack2h(c[2 * sl][0],     c[2 * sl][1]);
                    af[1] = pack2h(c[2 * sl][2],     c[2 * sl][3]);
                    af[2] = pack2h(c[2 * sl + 1][0], c[2 * sl + 1][1]);
                    af[3] = pack2h(c[2 * sl + 1][2], c[2 * sl + 1][3]);
                    uint32_t vrow = va0 + ((uint32_t)(2 * h + sl) << 11);
                    #pragma unroll
                    for (int p = 0; p < 4; p++) {
                        uint32_t bhr[4];
                        ldsm4t(bhr, Vc + (vrow ^ (cbv | (p << 5))));
                        mma_f16(o[2 * p],     af, bhr[0], bhr[1]);
                        mma_f16(o[2 * p + 1], af, bhr[2], bhr[3]);
                    }
                }
            }

            if (hasNext) {
                #pragma unroll
                for (int u = 0; u < 2; u++) {
                    uint32_t off = cvt0 + (2 * h + u) * 2048;
                    *(uint2*)(sm + KBUF(nxt) + off) = make_uint2(
                        pack2h(pk[u].x, pk[u].y), pack2h(pk[u].z, pk[u].w));
                    *(uint2*)(sm + VBUF(nxt) + off) = make_uint2(
                        pack2h(pv[u].x, pv[u].y), pack2h(pv[u].z, pv[u].w));
                }
            }
        }
        __syncthreads();
    }

    // rowsums -> l, O store (scaled, streaming)
    rsl += __shfl_xor_sync(0xffffffffu, rsl, 1);
    rsl += __shfl_xor_sync(0xffffffffu, rsl, 2);
    rsh += __shfl_xor_sync(0xffffffffu, rsh, 1);
    rsh += __shfl_xor_sync(0xffffffffu, rsh, 2);
    const float il = (rsl > 0.f) ? (1.f / rsl) : 0.f;
    const float ih = (rsh > 0.f) ? (1.f / rsh) : 0.f;
    if ((lane & 3) == 0) {
        g_l[bh * SEQ + qrl] = rsl;
        g_l[bh * SEQ + qrh] = rsh;
    }

    #pragma unroll
    for (int j = 0; j < 8; j++) {
        __stcs((float2*)(O + ((size_t)bh * SEQ + qrl) * HD + j * 8 + dcol),
               make_float2(o[j][0] * il, o[j][1] * il));
        __stcs((float2*)(O + ((size_t)bh * SEQ + qrh) * HD + j * 8 + dcol),
               make_float2(o[j][2] * ih, o[j][3] * ih));
    }
}

// ===========================================================================
// PHASE 2 kernel: recompute scores, P = ex2(score + log2(1/l)) stored via
// coalescing slab. smem: slabs 0..24K (overlaying the Q plane, which is dead
// after fragment hoist), K dbuf 24K..56K. 3 CTAs/SM.
// ===========================================================================
#define KBUF2(b) (24576u + (b) * 16384u)

__global__ __launch_bounds__(256, 3) void k_p2(
    const float* __restrict__ Q, const float* __restrict__ K,
    const int* __restrict__ mask_now, float* __restrict__ P)
{
    extern __shared__ char sm[];
    const uint32_t smb = smem_u32(sm);
    const int tid = threadIdx.x, lane = tid & 31, warp = tid >> 5;
    const int g = lane >> 3, r8 = lane & 7;
    const int qt = 15 - blockIdx.x, bh = blockIdx.y;
    const int q0 = qt * 128;
    const int mn = mask_now[0];

    const int base_elem = (tid >> 4) * HD + (tid & 15) * 4;
    const uint32_t cvt0 = SWZ((uint32_t)((tid >> 4) * 128 + (tid & 15) * 8));

    // stage Q (pre-scaled) at smem 0, K tile 0 at KBUF2(0)
    {
        const float* Qg = Q + ((size_t)bh * SEQ + q0) * HD + base_elem;
        const float* Kg = K + (size_t)bh * SEQ * HD + base_elem;
        #pragma unroll
        for (int s = 0; s < 8; s++) {
            uint32_t off = cvt0 + s * 2048;
            float4 v = *(const float4*)(Qg + s * 1024);
            *(uint2*)(sm + 0 + off) = make_uint2(
                pack2h(v.x * QSCALE, v.y * QSCALE),
                pack2h(v.z * QSCALE, v.w * QSCALE));
            v = *(const float4*)(Kg + s * 1024);
            *(uint2*)(sm + KBUF2(0) + off) = make_uint2(
                pack2h(v.x, v.y), pack2h(v.z, v.w));
        }
    }

    const int rl = warp * 16 + (lane >> 2), rh = rl + 8;
    const int qrl = q0 + rl, qrh = q0 + rh;
    const int dcol = 2 * (lane & 3);
    const int tcl = qrl - mn - dcol;
    const int tch = qrh - mn - dcol;
    const float ll = g_l[bh * SEQ + qrl];
    const float lh = g_l[bh * SEQ + qrh];
    const float lbl = (ll > 0.f) ? -__log2f(ll) : NEG_INF;
    const float lbh = (lh > 0.f) ? -__log2f(lh) : NEG_INF;

    const uint32_t cbq = (uint32_t)(lane & 8) << 1;
    const uint32_t cbv = (uint32_t)(g >> 1) << 4;
    const uint32_t ka0 = swzrow(((g >> 1) << 3) + r8);
    const uint32_t qrowswz = swzrow(warp * 16 + ((g & 1) << 3) + r8);

    __syncthreads();

    uint32_t qf[4][4];
    #pragma unroll
    for (int s = 0; s < 4; s++)
        ldsm4(qf[s], smb + (qrowswz ^ (cbv | (s << 5))));

    __syncthreads();   // Q plane dead; slabs may now overlay it

    // slab: per-warp 3072B (16 rows x 192B), region 0..24K
    const int r_l = lane >> 2;
    const int WSo = warp * 3072;
    const uint32_t xsw = (uint32_t)(r_l & 3) << 4;
    char* const slab_l = sm + WSo + r_l * 192;
    char* const slab_h = slab_l + 8 * 192;
    const int drow = lane >> 3;
    const uint32_t dgr = (uint32_t)((lane & 7) ^ drow) << 4;
    char* const drn = sm + WSo + drow * 192 + dgr;
    float* const Pst = P + ((size_t)bh * SEQ + q0 + warp * 16 + drow) * SEQ
                         + (lane & 7) * 4;
    float2* const Prl = (float2*)(P + ((size_t)bh * SEQ + qrl) * SEQ) + (lane & 3);
    float2* const Prh = (float2*)(P + ((size_t)bh * SEQ + qrh) * SEQ) + (lane & 3);

    for (int t = 0; t <= qt; t++) {
        const int cur = t & 1, nxt = cur ^ 1;
        const bool hasNext = (t < qt);
        const uint32_t Kc = smb + KBUF2(cur);
        const int k0 = t * 128;
        const bool diag = (t == qt);
        const float* Kg = K + ((size_t)bh * SEQ + k0 + 128) * HD + base_elem;

        #pragma unroll
        for (int h = 0; h < 4; h++) {
            float4 pk[2];
            if (hasNext) {
                #pragma unroll
                for (int u = 0; u < 2; u++)
                    pk[u] = *(const float4*)(Kg + (2 * h + u) * 1024);
            }

            if (diag && (2 * h > warp)) {
                #pragma unroll
                for (int jl = 0; jl < 4; jl++) {
                    __stcs(Prl + (k0 >> 1) + h * 16 + jl * 4, make_float2(0.f, 0.f));
                    __stcs(Prh + (k0 >> 1) + h * 16 + jl * 4, make_float2(0.f, 0.f));
                }
            } else {
                float c[4][4];
                #pragma unroll
                for (int j = 0; j < 4; j++) {
                    c[j][0] = c[j][1] = lbl;
                    c[j][2] = c[j][3] = lbh;
                }

                #pragma unroll
                for (int s = 0; s < 4; s++) {
                    #pragma unroll
                    for (int pp = 0; pp < 2; pp++) {
                        uint32_t kh[4];
                        ldsm4(kh, Kc + ((ka0 + ((uint32_t)(2 * h + pp) << 11)) ^ (cbq | (s << 5))));
                        mma_f16(c[2 * pp],     qf[s], kh[0], kh[1]);
                        mma_f16(c[2 * pp + 1], qf[s], kh[2], kh[3]);
                    }
                }

                __syncwarp();
                if (!diag) {
                    #pragma unroll
                    for (int jl = 0; jl < 4; jl++) {
                        uint32_t co = (uint32_t)(jl * 32 + dcol * 4) ^ xsw;
                        *(float2*)(slab_l + co) =
                            make_float2(ex2(c[jl][0]), ex2(c[jl][1]));
                        *(float2*)(slab_h + co) =
                            make_float2(ex2(c[jl][2]), ex2(c[jl][3]));
                    }
                } else {
                    #pragma unroll
                    for (int jl = 0; jl < 4; jl++) {
                        int bs = k0 + h * 32 + jl * 8;
                        uint32_t co = (uint32_t)(jl * 32 + dcol * 4) ^ xsw;
                        *(float2*)(slab_l + co) = make_float2(
                            (bs <= tcl    ) ? ex2(c[jl][0]) : 0.f,
                            (bs <= tcl - 1) ? ex2(c[jl][1]) : 0.f);
                        *(float2*)(slab_h + co) = make_float2(
                            (bs <= tch    ) ? ex2(c[jl][2]) : 0.f,
                            (bs <= tch - 1) ? ex2(c[jl][3]) : 0.f);
                    }
                }
                __syncwarp();
                #pragma unroll
                for (int i = 0; i < 2; i++) {
                    float4 f0 = *(float4*)(drn + i * 768);
                    float4 f1 = *(float4*)(drn + i * 768 + 1536);
                    __stcs((float4*)(Pst + (size_t)i * 4 * SEQ + k0 + h * 32), f0);
                    __stcs((float4*)(Pst + (size_t)i * 4 * SEQ + 8 * SEQ + k0 + h * 32), f1);
                }
            }

            if (hasNext) {
                #pragma unroll
                for (int u = 0; u < 2; u++) {
                    uint32_t off = cvt0 + (2 * h + u) * 2048;
                    *(uint2*)(sm + KBUF2(nxt) + off) = make_uint2(
                        pack2h(pk[u].x, pk[u].y), pack2h(pk[u].z, pk[u].w));
                }
            }
        }
        __syncthreads();
    }
}

// ---------------------------------------------------------------------------
extern "C" void kernel_launch(void* const* d_in, const int* in_sizes, int n_in,
                              void* d_out, int out_size)
{
    const float* Q        = (const float*)d_in[0];
    const float* K        = (const float*)d_in[1];
    const float* V        = (const float*)d_in[2];
    const float* mask     = (const float*)d_in[3];
    const int*   mask_now = (const int*)d_in[4];

    float* O = (float*)d_out;                      // [B,H,S,D]
    float* P = O + (size_t)NBH * SEQ * HD;         // [B,H,S,S]

    cudaFuncSetAttribute(k_p1, cudaFuncAttributeMaxDynamicSharedMemorySize, 81920);
    cudaFuncSetAttribute(k_p2, cudaFuncAttributeMaxDynamicSharedMemorySize, 57344);

    k_p1<<<dim3(16, NBH), 256, 81920>>>(Q, K, V, mask, mask_now, P, O);
    k_p2<<<dim3(16, NBH), 256, 57344>>>(Q, K, mask_now, P);
}